// round 1
// baseline (speedup 1.0000x reference)
#include <cuda_runtime.h>
#include <cuda_bf16.h>
#include <math.h>

// Problem constants
#define HIDDEN   2560
#define NUM_HEADS 8
#define HEAD_DIM 512
#define SEQ      32768
#define QROWS    (NUM_HEADS * HEAD_DIM)   // 4096
#define SCALE    0.04419417382415922f     // 1/sqrt(512)

#define CHUNK    128                      // keys per PV block
#define NCHUNK   (SEQ / CHUNK)            // 256

// ------------------------- device scratch (no allocs allowed) ---------------
__device__ float g_q[QROWS];
__device__ float g_k[HEAD_DIM];
__device__ float g_v[HEAD_DIM];
__device__ float g_scores[NUM_HEADS * SEQ];      // 1 MB
__device__ float g_m[NUM_HEADS];
__device__ float g_l[NUM_HEADS];
__device__ float g_partial[NCHUNK * QROWS];      // 4 MB
__device__ float g_attn[QROWS];

// ------------------------- helpers ------------------------------------------
__device__ __forceinline__ float warp_sum(float v) {
    #pragma unroll
    for (int o = 16; o; o >>= 1) v += __shfl_xor_sync(0xffffffffu, v, o);
    return v;
}

// ------------------------- kernel 1: fused QKV GEMV --------------------------
// grid = 5120 blocks (4096 q rows, 512 k rows, 512 v rows), 256 threads.
__global__ void qkv_gemv(const float* __restrict__ x,
                         const float* __restrict__ wq,
                         const float* __restrict__ wk,
                         const float* __restrict__ wv) {
    int r = blockIdx.x;
    const float* w;
    float* out;
    if (r < QROWS)            { w = wq + (size_t)r * HIDDEN;            out = g_q + r; }
    else if (r < QROWS + 512) { w = wk + (size_t)(r - QROWS) * HIDDEN;  out = g_k + (r - QROWS); }
    else                      { w = wv + (size_t)(r - QROWS - 512) * HIDDEN; out = g_v + (r - QROWS - 512); }

    const float4* w4 = reinterpret_cast<const float4*>(w);
    const float4* x4 = reinterpret_cast<const float4*>(x);
    float s = 0.f;
    #pragma unroll 2
    for (int i = threadIdx.x; i < HIDDEN / 4; i += 256) {
        float4 a = w4[i];
        float4 b = x4[i];
        s += a.x * b.x + a.y * b.y + a.z * b.z + a.w * b.w;
    }
    __shared__ float sh[8];
    int lane = threadIdx.x & 31, warp = threadIdx.x >> 5;
    s = warp_sum(s);
    if (lane == 0) sh[warp] = s;
    __syncthreads();
    if (warp == 0) {
        s = (lane < 8) ? sh[lane] : 0.f;
        s = warp_sum(s);
        if (lane == 0) *out = s;
    }
}

// ------------------------- kernel 2: scores ----------------------------------
// 1024 blocks x 256 thr. Each block: 8 warps x 4 keys = 32 keys.
// q (8x512, 16 KB) cached in smem; each key row read once, reused by 8 heads.
__global__ void scores_kernel(const float* __restrict__ kv_full,
                              const int* __restrict__ cur_pos) {
    __shared__ __align__(16) float qs[NUM_HEADS * HEAD_DIM];
    for (int i = threadIdx.x; i < NUM_HEADS * HEAD_DIM; i += 256) qs[i] = g_q[i];
    __syncthreads();

    int warp = threadIdx.x >> 5, lane = threadIdx.x & 31;
    int cp = cur_pos[0];
    int jbase = blockIdx.x * 32 + warp * 4;

    for (int t = 0; t < 4; t++) {
        int j = jbase + t;
        const float* krow = (j == cp) ? g_k : (kv_full + (size_t)j * HEAD_DIM);
        float sums[NUM_HEADS];
        #pragma unroll
        for (int h = 0; h < NUM_HEADS; h++) sums[h] = 0.f;

        #pragma unroll
        for (int i = 0; i < 4; i++) {
            int d = i * 128 + lane * 4;
            float4 kv = *reinterpret_cast<const float4*>(krow + d);
            #pragma unroll
            for (int h = 0; h < NUM_HEADS; h++) {
                float4 qv = *reinterpret_cast<const float4*>(qs + h * HEAD_DIM + d);
                sums[h] += qv.x * kv.x + qv.y * kv.y + qv.z * kv.z + qv.w * kv.w;
            }
        }
        #pragma unroll
        for (int h = 0; h < NUM_HEADS; h++) {
            float s = warp_sum(sums[h]);
            if (lane == 0) g_scores[h * SEQ + j] = s * SCALE;
        }
    }
}

// ------------------------- kernel 3: per-head softmax stats ------------------
// 8 blocks (one per head), 512 threads.
__global__ void softmax_stats() {
    int h = blockIdx.x;
    const float* s = g_scores + (size_t)h * SEQ;
    __shared__ float red[16];
    __shared__ float bm;
    int lane = threadIdx.x & 31, warp = threadIdx.x >> 5;

    // max
    float m = -INFINITY;
    for (int i = threadIdx.x; i < SEQ; i += 512) m = fmaxf(m, s[i]);
    #pragma unroll
    for (int o = 16; o; o >>= 1) m = fmaxf(m, __shfl_xor_sync(0xffffffffu, m, o));
    if (lane == 0) red[warp] = m;
    __syncthreads();
    if (threadIdx.x == 0) {
        float mm = red[0];
        for (int i = 1; i < 16; i++) mm = fmaxf(mm, red[i]);
        bm = mm;
    }
    __syncthreads();
    m = bm;

    // sum of exp
    float l = 0.f;
    for (int i = threadIdx.x; i < SEQ; i += 512) l += expf(s[i] - m);
    l = warp_sum(l);
    __syncthreads();
    if (lane == 0) red[warp] = l;
    __syncthreads();
    if (threadIdx.x == 0) {
        float ll = 0.f;
        for (int i = 0; i < 16; i++) ll += red[i];
        g_m[h] = m;
        g_l[h] = ll;
    }
}

// ------------------------- kernel 4: P @ V (split-K, deterministic) ----------
// 256 blocks x 256 thr. Each block: 128 keys, full 512-dim for all 8 heads.
// Thread owns float2 of d-dim per head; partials to g_partial.
__global__ void pv_kernel(const float* __restrict__ kv_full,
                          const int* __restrict__ cur_pos) {
    const float* vcache = kv_full + (size_t)SEQ * HEAD_DIM;
    int j0 = blockIdx.x * CHUNK;
    int cp = cur_pos[0];

    __shared__ float p[NUM_HEADS * CHUNK];
    for (int i = threadIdx.x; i < NUM_HEADS * CHUNK; i += 256) {
        int h = i >> 7;        // /128
        int jj = i & (CHUNK - 1);
        p[i] = expf(g_scores[h * SEQ + j0 + jj] - g_m[h]);
    }
    __syncthreads();

    int d = threadIdx.x * 2;
    float2 acc[NUM_HEADS];
    #pragma unroll
    for (int h = 0; h < NUM_HEADS; h++) acc[h] = make_float2(0.f, 0.f);

    for (int jj = 0; jj < CHUNK; jj++) {
        int j = j0 + jj;
        const float* vrow = (j == cp) ? g_v : (vcache + (size_t)j * HEAD_DIM);
        float2 vv = *reinterpret_cast<const float2*>(vrow + d);
        #pragma unroll
        for (int h = 0; h < NUM_HEADS; h++) {
            float pw = p[h * CHUNK + jj];
            acc[h].x = fmaf(pw, vv.x, acc[h].x);
            acc[h].y = fmaf(pw, vv.y, acc[h].y);
        }
    }
    float* out = g_partial + (size_t)blockIdx.x * QROWS;
    #pragma unroll
    for (int h = 0; h < NUM_HEADS; h++) {
        out[h * HEAD_DIM + d]     = acc[h].x;
        out[h * HEAD_DIM + d + 1] = acc[h].y;
    }
}

// ------------------------- kernel 5: partial reduce + normalize --------------
// 16 blocks x 256 thr; each thread owns one of 4096 outputs; fixed-order sum.
__global__ void pv_reduce() {
    int idx = blockIdx.x * 256 + threadIdx.x;   // 0..4095
    int h = idx >> 9;                           // /512
    float s = 0.f;
    #pragma unroll 4
    for (int c = 0; c < NCHUNK; c++) s += g_partial[(size_t)c * QROWS + idx];
    g_attn[idx] = s / g_l[h];
}

// ------------------------- kernel 6: output GEMV -----------------------------
// 2560 blocks x 256 thr: out[r] = dot(wo[r,:], attn)
__global__ void wo_gemv(const float* __restrict__ wo, float* __restrict__ out) {
    int r = blockIdx.x;
    const float4* w4 = reinterpret_cast<const float4*>(wo + (size_t)r * QROWS);
    const float4* a4 = reinterpret_cast<const float4*>(g_attn);
    float s = 0.f;
    #pragma unroll 2
    for (int i = threadIdx.x; i < QROWS / 4; i += 256) {
        float4 a = w4[i];
        float4 b = a4[i];
        s += a.x * b.x + a.y * b.y + a.z * b.z + a.w * b.w;
    }
    __shared__ float sh[8];
    int lane = threadIdx.x & 31, warp = threadIdx.x >> 5;
    s = warp_sum(s);
    if (lane == 0) sh[warp] = s;
    __syncthreads();
    if (warp == 0) {
        s = (lane < 8) ? sh[lane] : 0.f;
        s = warp_sum(s);
        if (lane == 0) out[r] = s;
    }
}

// ------------------------- launch -------------------------------------------
extern "C" void kernel_launch(void* const* d_in, const int* in_sizes, int n_in,
                              void* d_out, int out_size) {
    const float* x       = (const float*)d_in[0];
    // d_in[1] = kv_sliding (unused by reference math)
    const float* kv_full = (const float*)d_in[2];
    const float* wq      = (const float*)d_in[3];
    const float* wk      = (const float*)d_in[4];
    const float* wv      = (const float*)d_in[5];
    const float* wo      = (const float*)d_in[6];
    const int*   curpos  = (const int*)d_in[7];
    // d_in[8] = ring_pos (unused)
    float* out = (float*)d_out;

    qkv_gemv<<<QROWS + 1024, 256>>>(x, wq, wk, wv);
    scores_kernel<<<SEQ / 32, 256>>>(kv_full, curpos);
    softmax_stats<<<NUM_HEADS, 512>>>();
    pv_kernel<<<NCHUNK, 256>>>(kv_full, curpos);
    pv_reduce<<<QROWS / 256, 256>>>();
    wo_gemv<<<HIDDEN, 256>>>(wo, out);
}

// round 4
// speedup vs baseline: 1.0804x; 1.0804x over previous
#include <cuda_runtime.h>
#include <cuda_bf16.h>
#include <math.h>

// Problem constants
#define HIDDEN    2560
#define NUM_HEADS 8
#define HEAD_DIM  512
#define SEQ       32768
#define QROWS     (NUM_HEADS * HEAD_DIM)   // 4096
#define SCALE     0.04419417382415922f     // 1/sqrt(512)

#define CHUNK     64                       // keys per attention block
#define NCHUNK    (SEQ / CHUNK)            // 512 blocks
#define NGROUP    8                        // reduce groups
#define GSZ       (NCHUNK / NGROUP)        // 64 chunks per group

// ------------------------- device scratch (no allocs allowed) ---------------
__device__ float g_q[QROWS];
__device__ float g_k[HEAD_DIM];
__device__ float g_v[HEAD_DIM];
__device__ float g_pm[NCHUNK * NUM_HEADS];          // per-chunk max
__device__ float g_pl[NCHUNK * NUM_HEADS];          // per-chunk expsum
__device__ float g_w[NUM_HEADS * NCHUNK];           // combine weights
__device__ float g_pacc[(size_t)NCHUNK * QROWS];    // 8 MB partial PV
__device__ float g_pacc2[(size_t)NGROUP * QROWS];   // 128 KB
__device__ float g_attn[QROWS];

// ------------------------- helpers ------------------------------------------
__device__ __forceinline__ float warp_sum(float v) {
    #pragma unroll
    for (int o = 16; o; o >>= 1) v += __shfl_xor_sync(0xffffffffu, v, o);
    return v;
}
__device__ __forceinline__ float warp_max(float v) {
    #pragma unroll
    for (int o = 16; o; o >>= 1) v = fmaxf(v, __shfl_xor_sync(0xffffffffu, v, o));
    return v;
}

// ------------------------- kernel 1: fused QKV GEMV --------------------------
__global__ void qkv_gemv(const float* __restrict__ x,
                         const float* __restrict__ wq,
                         const float* __restrict__ wk,
                         const float* __restrict__ wv) {
    int r = blockIdx.x;
    const float* w;
    float* out;
    if (r < QROWS)            { w = wq + (size_t)r * HIDDEN;                 out = g_q + r; }
    else if (r < QROWS + 512) { w = wk + (size_t)(r - QROWS) * HIDDEN;       out = g_k + (r - QROWS); }
    else                      { w = wv + (size_t)(r - QROWS - 512) * HIDDEN; out = g_v + (r - QROWS - 512); }

    const float4* w4 = reinterpret_cast<const float4*>(w);
    const float4* x4 = reinterpret_cast<const float4*>(x);
    float s = 0.f;
    #pragma unroll 3
    for (int i = threadIdx.x; i < HIDDEN / 4; i += 256) {
        float4 a = w4[i];
        float4 b = x4[i];
        s += a.x * b.x + a.y * b.y + a.z * b.z + a.w * b.w;
    }
    __shared__ float sh[8];
    int lane = threadIdx.x & 31, warp = threadIdx.x >> 5;
    s = warp_sum(s);
    if (lane == 0) sh[warp] = s;
    __syncthreads();
    if (warp == 0) {
        s = (lane < 8) ? sh[lane] : 0.f;
        s = warp_sum(s);
        if (lane == 0) *out = s;
    }
}

// ------------------------- kernel 2: fused flash-decode chunk ----------------
// 512 blocks x 256 threads. Each block: 64 keys.
// Phase A: scores (8 warps x 8 keys, 4 keys concurrently per warp).
// Phase B: local softmax stats per head.
// Phase C: P@V partial accumulation (thread owns float2 of d).
__global__ void __launch_bounds__(256)
attn_chunk(const float* __restrict__ kv_full, const int* __restrict__ cur_pos) {
    __shared__ __align__(16) float qs[QROWS];          // 16 KB
    __shared__ float p[NUM_HEADS][CHUNK];              // scores -> probs, 2 KB

    for (int i = threadIdx.x; i < QROWS; i += 256) qs[i] = g_q[i];
    __syncthreads();

    const int warp = threadIdx.x >> 5, lane = threadIdx.x & 31;
    const int cp = cur_pos[0];
    const int j0 = blockIdx.x * CHUNK;

    // ---- Phase A: scores ----
    #pragma unroll
    for (int g = 0; g < 2; g++) {
        const int jj = warp * 8 + g * 4;
        const float* kr[4];
        #pragma unroll
        for (int t = 0; t < 4; t++) {
            int j = j0 + jj + t;
            kr[t] = (j == cp) ? g_k : (kv_full + (size_t)j * HEAD_DIM);
        }
        float acc[NUM_HEADS][4];
        #pragma unroll
        for (int h = 0; h < NUM_HEADS; h++)
            #pragma unroll
            for (int t = 0; t < 4; t++) acc[h][t] = 0.f;

        #pragma unroll
        for (int i = 0; i < 4; i++) {
            int d = i * 128 + lane * 4;
            float4 kv0 = *reinterpret_cast<const float4*>(kr[0] + d);
            float4 kv1 = *reinterpret_cast<const float4*>(kr[1] + d);
            float4 kv2 = *reinterpret_cast<const float4*>(kr[2] + d);
            float4 kv3 = *reinterpret_cast<const float4*>(kr[3] + d);
            #pragma unroll
            for (int h = 0; h < NUM_HEADS; h++) {
                float4 qv = *reinterpret_cast<const float4*>(qs + h * HEAD_DIM + d);
                acc[h][0] += qv.x * kv0.x + qv.y * kv0.y + qv.z * kv0.z + qv.w * kv0.w;
                acc[h][1] += qv.x * kv1.x + qv.y * kv1.y + qv.z * kv1.z + qv.w * kv1.w;
                acc[h][2] += qv.x * kv2.x + qv.y * kv2.y + qv.z * kv2.z + qv.w * kv2.w;
                acc[h][3] += qv.x * kv3.x + qv.y * kv3.y + qv.z * kv3.z + qv.w * kv3.w;
            }
        }
        #pragma unroll
        for (int h = 0; h < NUM_HEADS; h++) {
            #pragma unroll
            for (int t = 0; t < 4; t++) {
                float s = warp_sum(acc[h][t]);
                if (lane == 0) p[h][jj + t] = s * SCALE;
            }
        }
    }
    __syncthreads();

    // ---- Phase B: local softmax stats (warp h handles head h) ----
    {
        const int h = warp;   // 8 warps, 8 heads
        float a = p[h][lane];
        float b = p[h][lane + 32];
        float m = warp_max(fmaxf(a, b));
        float ea = __expf(a - m);
        float eb = __expf(b - m);
        float l = warp_sum(ea + eb);
        p[h][lane]      = ea;
        p[h][lane + 32] = eb;
        if (lane == 0) {
            g_pm[blockIdx.x * NUM_HEADS + h] = m;
            g_pl[blockIdx.x * NUM_HEADS + h] = l;
        }
    }
    __syncthreads();

    // ---- Phase C: P @ V partial ----
    const int d = threadIdx.x * 2;
    const float* vcache = kv_full + (size_t)SEQ * HEAD_DIM;
    float2 acc2[NUM_HEADS];
    #pragma unroll
    for (int h = 0; h < NUM_HEADS; h++) acc2[h] = make_float2(0.f, 0.f);

    #pragma unroll 4
    for (int jj = 0; jj < CHUNK; jj++) {
        int j = j0 + jj;
        const float* vrow = (j == cp) ? g_v : (vcache + (size_t)j * HEAD_DIM);
        float2 vv = *reinterpret_cast<const float2*>(vrow + d);
        #pragma unroll
        for (int h = 0; h < NUM_HEADS; h++) {
            float pw = p[h][jj];
            acc2[h].x = fmaf(pw, vv.x, acc2[h].x);
            acc2[h].y = fmaf(pw, vv.y, acc2[h].y);
        }
    }
    float* o = g_pacc + (size_t)blockIdx.x * QROWS;
    #pragma unroll
    for (int h = 0; h < NUM_HEADS; h++)
        *reinterpret_cast<float2*>(o + h * HEAD_DIM + d) = acc2[h];
}

// ------------------------- kernel 3: global softmax combine weights ----------
// 8 blocks (head each) x 512 threads (one per chunk).
__global__ void stats_kernel() {
    const int h = blockIdx.x;
    const int c = threadIdx.x;            // 512 == NCHUNK
    __shared__ float red[16];
    __shared__ float sM, sL;
    int lane = c & 31, warp = c >> 5;

    float m = g_pm[c * NUM_HEADS + h];
    float l = g_pl[c * NUM_HEADS + h];

    float mm = warp_max(m);
    if (lane == 0) red[warp] = mm;
    __syncthreads();
    if (c == 0) {
        float M = red[0];
        #pragma unroll
        for (int i = 1; i < 16; i++) M = fmaxf(M, red[i]);
        sM = M;
    }
    __syncthreads();
    float e = __expf(m - sM);
    float le = warp_sum(l * e);
    __syncthreads();
    if (lane == 0) red[warp] = le;
    __syncthreads();
    if (c == 0) {
        float L = 0.f;
        #pragma unroll
        for (int i = 0; i < 16; i++) L += red[i];
        sL = L;
    }
    __syncthreads();
    g_w[h * NCHUNK + c] = e / sL;
}

// ------------------------- kernel 4: weighted partial reduce (level 1) -------
// 128 blocks (8 groups x 16 idx-blocks) x 256 threads.
__global__ void reduce1() {
    const int g  = blockIdx.x >> 4;
    const int ib = blockIdx.x & 15;
    const int idx = ib * 256 + threadIdx.x;     // 0..4095
    const int h = idx >> 9;
    __shared__ float w[GSZ];
    if (threadIdx.x < GSZ) w[threadIdx.x] = g_w[h * NCHUNK + g * GSZ + threadIdx.x];
    __syncthreads();

    float s = 0.f;
    #pragma unroll 8
    for (int cc = 0; cc < GSZ; cc++)
        s += w[cc] * g_pacc[(size_t)(g * GSZ + cc) * QROWS + idx];
    g_pacc2[(size_t)g * QROWS + idx] = s;
}

// ------------------------- kernel 5: reduce level 2 --------------------------
__global__ void reduce2() {
    const int idx = blockIdx.x * 256 + threadIdx.x;
    float s = 0.f;
    #pragma unroll
    for (int g = 0; g < NGROUP; g++) s += g_pacc2[(size_t)g * QROWS + idx];
    g_attn[idx] = s;
}

// ------------------------- kernel 6: output GEMV -----------------------------
__global__ void wo_gemv(const float* __restrict__ wo, float* __restrict__ out) {
    int r = blockIdx.x;
    const float4* w4 = reinterpret_cast<const float4*>(wo + (size_t)r * QROWS);
    const float4* a4 = reinterpret_cast<const float4*>(g_attn);
    float s = 0.f;
    #pragma unroll 4
    for (int i = threadIdx.x; i < QROWS / 4; i += 256) {
        float4 a = w4[i];
        float4 b = a4[i];
        s += a.x * b.x + a.y * b.y + a.z * b.z + a.w * b.w;
    }
    __shared__ float sh[8];
    int lane = threadIdx.x & 31, warp = threadIdx.x >> 5;
    s = warp_sum(s);
    if (lane == 0) sh[warp] = s;
    __syncthreads();
    if (warp == 0) {
        s = (lane < 8) ? sh[lane] : 0.f;
        s = warp_sum(s);
        if (lane == 0) out[r] = s;
    }
}

// ------------------------- launch -------------------------------------------
extern "C" void kernel_launch(void* const* d_in, const int* in_sizes, int n_in,
                              void* d_out, int out_size) {
    const float* x       = (const float*)d_in[0];
    // d_in[1] = kv_sliding (unused by reference math)
    const float* kv_full = (const float*)d_in[2];
    const float* wq      = (const float*)d_in[3];
    const float* wk      = (const float*)d_in[4];
    const float* wv      = (const float*)d_in[5];
    const float* wo      = (const float*)d_in[6];
    const int*   curpos  = (const int*)d_in[7];
    // d_in[8] = ring_pos (unused)
    float* out = (float*)d_out;

    qkv_gemv<<<QROWS + 1024, 256>>>(x, wq, wk, wv);
    attn_chunk<<<NCHUNK, 256>>>(kv_full, curpos);
    stats_kernel<<<NUM_HEADS, 512>>>();
    reduce1<<<NGROUP * 16, 256>>>();
    reduce2<<<QROWS / 256, 256>>>();
    wo_gemv<<<HIDDEN, 256>>>(wo, out);
}

// round 5
// speedup vs baseline: 1.3761x; 1.2737x over previous
#include <cuda_runtime.h>
#include <cuda_bf16.h>
#include <math.h>

// Problem constants
#define HIDDEN    2560
#define NUM_HEADS 8
#define HEAD_DIM  512
#define SEQ       32768
#define QROWS     (NUM_HEADS * HEAD_DIM)   // 4096
#define SCALE     0.04419417382415922f     // 1/sqrt(512)

#define CHUNK     64                       // keys per attention block
#define NCHUNK    (SEQ / CHUNK)            // 512 blocks
#define NGROUP    16                       // reduce groups
#define GSZ       (NCHUNK / NGROUP)        // 32 chunks per group

// ------------------------- device scratch (no allocs allowed) ---------------
__device__ float g_q[QROWS];
__device__ float g_k[HEAD_DIM];
__device__ float g_v[HEAD_DIM];
__device__ float g_pm[NCHUNK * NUM_HEADS];          // per-chunk max
__device__ float g_pl[NCHUNK * NUM_HEADS];          // per-chunk expsum
__device__ float g_pacc[(size_t)NCHUNK * QROWS];    // 8 MB partial PV
__device__ float g_pacc2[(size_t)NGROUP * QROWS];   // 256 KB
__device__ float g_attn[QROWS];

// ------------------------- helpers ------------------------------------------
__device__ __forceinline__ float warp_sum(float v) {
    #pragma unroll
    for (int o = 16; o; o >>= 1) v += __shfl_xor_sync(0xffffffffu, v, o);
    return v;
}
__device__ __forceinline__ float warp_max(float v) {
    #pragma unroll
    for (int o = 16; o; o >>= 1) v = fmaxf(v, __shfl_xor_sync(0xffffffffu, v, o));
    return v;
}

// ------------------------- kernel 1: fused QKV GEMV (warp-per-row) -----------
// 160 blocks x 1024 threads = 5120 warps; warp w handles row w.
// Each lane: 20 independent float4 loads (320B in flight).
__global__ void __launch_bounds__(1024)
qkv_gemv(const float* __restrict__ x,
         const float* __restrict__ wq,
         const float* __restrict__ wk,
         const float* __restrict__ wv) {
    int r = blockIdx.x * 32 + (threadIdx.x >> 5);
    int lane = threadIdx.x & 31;
    const float* w;
    float* out;
    if (r < QROWS)            { w = wq + (size_t)r * HIDDEN;                 out = g_q + r; }
    else if (r < QROWS + 512) { w = wk + (size_t)(r - QROWS) * HIDDEN;       out = g_k + (r - QROWS); }
    else                      { w = wv + (size_t)(r - QROWS - 512) * HIDDEN; out = g_v + (r - QROWS - 512); }

    const float4* w4 = reinterpret_cast<const float4*>(w);
    const float4* x4 = reinterpret_cast<const float4*>(x);
    float s = 0.f;
    #pragma unroll
    for (int i = 0; i < HIDDEN / 4 / 32; i++) {     // 20 iterations
        float4 a = w4[i * 32 + lane];
        float4 b = x4[i * 32 + lane];
        s += a.x * b.x + a.y * b.y + a.z * b.z + a.w * b.w;
    }
    s = warp_sum(s);
    if (lane == 0) *out = s;
}

// ------------------------- kernel 2: fused flash-decode chunk ----------------
// 512 blocks x 256 threads. Each block: 64 keys.
__global__ void __launch_bounds__(256)
attn_chunk(const float* __restrict__ kv_full, const int* __restrict__ cur_pos) {
    __shared__ __align__(16) float qs[QROWS];          // 16 KB (reused as combine buf)
    __shared__ float p[NUM_HEADS][CHUNK];              // scores -> probs, 2 KB

    for (int i = threadIdx.x; i < QROWS; i += 256) qs[i] = g_q[i];
    __syncthreads();

    const int warp = threadIdx.x >> 5, lane = threadIdx.x & 31;
    const int cp = cur_pos[0];
    const int j0 = blockIdx.x * CHUNK;

    // ---- Phase A: scores (8 warps x 8 keys; 4 keys concurrently per warp) ----
    #pragma unroll
    for (int g = 0; g < 2; g++) {
        const int jj = warp * 8 + g * 4;
        const float* kr[4];
        #pragma unroll
        for (int t = 0; t < 4; t++) {
            int j = j0 + jj + t;
            kr[t] = (j == cp) ? g_k : (kv_full + (size_t)j * HEAD_DIM);
        }
        float acc[NUM_HEADS][4];
        #pragma unroll
        for (int h = 0; h < NUM_HEADS; h++)
            #pragma unroll
            for (int t = 0; t < 4; t++) acc[h][t] = 0.f;

        #pragma unroll
        for (int i = 0; i < 4; i++) {
            int d = i * 128 + lane * 4;
            float4 kv0 = *reinterpret_cast<const float4*>(kr[0] + d);
            float4 kv1 = *reinterpret_cast<const float4*>(kr[1] + d);
            float4 kv2 = *reinterpret_cast<const float4*>(kr[2] + d);
            float4 kv3 = *reinterpret_cast<const float4*>(kr[3] + d);
            #pragma unroll
            for (int h = 0; h < NUM_HEADS; h++) {
                float4 qv = *reinterpret_cast<const float4*>(qs + h * HEAD_DIM + d);
                acc[h][0] += qv.x * kv0.x + qv.y * kv0.y + qv.z * kv0.z + qv.w * kv0.w;
                acc[h][1] += qv.x * kv1.x + qv.y * kv1.y + qv.z * kv1.z + qv.w * kv1.w;
                acc[h][2] += qv.x * kv2.x + qv.y * kv2.y + qv.z * kv2.z + qv.w * kv2.w;
                acc[h][3] += qv.x * kv3.x + qv.y * kv3.y + qv.z * kv3.z + qv.w * kv3.w;
            }
        }
        #pragma unroll
        for (int h = 0; h < NUM_HEADS; h++) {
            #pragma unroll
            for (int t = 0; t < 4; t++) {
                float s = warp_sum(acc[h][t]);
                if (lane == 0) p[h][jj + t] = s * SCALE;
            }
        }
    }
    __syncthreads();

    // ---- Phase B: local softmax stats (warp h handles head h) ----
    {
        const int h = warp;
        float a = p[h][lane];
        float b = p[h][lane + 32];
        float m = warp_max(fmaxf(a, b));
        float ea = __expf(a - m);
        float eb = __expf(b - m);
        float l = warp_sum(ea + eb);
        p[h][lane]      = ea;
        p[h][lane + 32] = eb;
        if (lane == 0) {
            g_pm[blockIdx.x * NUM_HEADS + h] = m;
            g_pl[blockIdx.x * NUM_HEADS + h] = l;
        }
    }
    __syncthreads();

    // ---- Phase C: P @ V partial (float4, jj split across thread halves) ----
    const int half = threadIdx.x >> 7;          // 0 or 1
    const int t    = threadIdx.x & 127;
    const int d    = t * 4;
    const int jbase = half * 32;
    const float* vcache = kv_full + (size_t)SEQ * HEAD_DIM;

    float4 acc4[NUM_HEADS];
    #pragma unroll
    for (int h = 0; h < NUM_HEADS; h++) acc4[h] = make_float4(0.f, 0.f, 0.f, 0.f);

    #pragma unroll 8
    for (int jj = 0; jj < 32; jj++) {
        int j = j0 + jbase + jj;
        const float* vrow = (j == cp) ? g_v : (vcache + (size_t)j * HEAD_DIM);
        float4 vv = *reinterpret_cast<const float4*>(vrow + d);
        #pragma unroll
        for (int h = 0; h < NUM_HEADS; h++) {
            float pw = p[h][jbase + jj];
            acc4[h].x = fmaf(pw, vv.x, acc4[h].x);
            acc4[h].y = fmaf(pw, vv.y, acc4[h].y);
            acc4[h].z = fmaf(pw, vv.z, acc4[h].z);
            acc4[h].w = fmaf(pw, vv.w, acc4[h].w);
        }
    }

    // combine halves via smem (reuse qs: 128 t x 8 h x float4 = 16 KB)
    __syncthreads();
    float4* cb = reinterpret_cast<float4*>(qs);
    if (half == 1) {
        #pragma unroll
        for (int h = 0; h < NUM_HEADS; h++) cb[h * 128 + t] = acc4[h];
    }
    __syncthreads();
    if (half == 0) {
        float* o = g_pacc + (size_t)blockIdx.x * QROWS;
        #pragma unroll
        for (int h = 0; h < NUM_HEADS; h++) {
            float4 b = cb[h * 128 + t];
            float4 r = acc4[h];
            r.x += b.x; r.y += b.y; r.z += b.z; r.w += b.w;
            *reinterpret_cast<float4*>(o + h * HEAD_DIM + d) = r;
        }
    }
}

// ------------------------- kernel 3: weighted reduce L1 (+ fused stats) ------
// 256 blocks x 256 thr. Block covers group g (32 chunks) x 256 outputs (one head).
__global__ void __launch_bounds__(256)
reduce1() {
    const int g  = blockIdx.x >> 4;             // 0..15
    const int ib = blockIdx.x & 15;             // 0..15
    const int idx = ib * 256 + threadIdx.x;     // 0..4095
    const int h = ib >> 1;                      // head for this whole block

    __shared__ float red[8];
    __shared__ float sM, sL;
    __shared__ float w[GSZ];
    const int lane = threadIdx.x & 31, warp = threadIdx.x >> 5;

    // global max over all 512 chunks for head h
    float m = fmaxf(g_pm[(threadIdx.x * 2) * NUM_HEADS + h],
                    g_pm[(threadIdx.x * 2 + 1) * NUM_HEADS + h]);
    m = warp_max(m);
    if (lane == 0) red[warp] = m;
    __syncthreads();
    if (threadIdx.x == 0) {
        float M = red[0];
        #pragma unroll
        for (int i = 1; i < 8; i++) M = fmaxf(M, red[i]);
        sM = M;
    }
    __syncthreads();
    // global L
    float l = g_pl[(threadIdx.x * 2) * NUM_HEADS + h] * __expf(g_pm[(threadIdx.x * 2) * NUM_HEADS + h] - sM)
            + g_pl[(threadIdx.x * 2 + 1) * NUM_HEADS + h] * __expf(g_pm[(threadIdx.x * 2 + 1) * NUM_HEADS + h] - sM);
    l = warp_sum(l);
    __syncthreads();
    if (lane == 0) red[warp] = l;
    __syncthreads();
    if (threadIdx.x == 0) {
        float L = 0.f;
        #pragma unroll
        for (int i = 0; i < 8; i++) L += red[i];
        sL = L;
    }
    __syncthreads();
    // combine weights for this group's chunks
    if (threadIdx.x < GSZ) {
        int c = g * GSZ + threadIdx.x;
        w[threadIdx.x] = __expf(g_pm[c * NUM_HEADS + h] - sM) / sL;
    }
    __syncthreads();

    float s = 0.f;
    #pragma unroll 8
    for (int cc = 0; cc < GSZ; cc++)
        s += w[cc] * g_pacc[(size_t)(g * GSZ + cc) * QROWS + idx];
    g_pacc2[(size_t)g * QROWS + idx] = s;
}

// ------------------------- kernel 4: reduce level 2 --------------------------
__global__ void reduce2() {
    const int idx = blockIdx.x * 256 + threadIdx.x;
    float s = 0.f;
    #pragma unroll
    for (int g = 0; g < NGROUP; g++) s += g_pacc2[(size_t)g * QROWS + idx];
    g_attn[idx] = s;
}

// ------------------------- kernel 5: output GEMV (warp-per-row) --------------
// 80 blocks x 1024 threads = 2560 warps; warp w handles row w.
__global__ void __launch_bounds__(1024)
wo_gemv(const float* __restrict__ wo, float* __restrict__ out) {
    int r = blockIdx.x * 32 + (threadIdx.x >> 5);
    int lane = threadIdx.x & 31;
    const float4* w4 = reinterpret_cast<const float4*>(wo + (size_t)r * QROWS);
    const float4* a4 = reinterpret_cast<const float4*>(g_attn);
    float s = 0.f;
    #pragma unroll
    for (int i = 0; i < QROWS / 4 / 32; i++) {      // 32 iterations
        float4 a = w4[i * 32 + lane];
        float4 b = a4[i * 32 + lane];
        s += a.x * b.x + a.y * b.y + a.z * b.z + a.w * b.w;
    }
    s = warp_sum(s);
    if (lane == 0) out[r] = s;
}

// ------------------------- launch -------------------------------------------
extern "C" void kernel_launch(void* const* d_in, const int* in_sizes, int n_in,
                              void* d_out, int out_size) {
    const float* x       = (const float*)d_in[0];
    // d_in[1] = kv_sliding (unused by reference math)
    const float* kv_full = (const float*)d_in[2];
    const float* wq      = (const float*)d_in[3];
    const float* wk      = (const float*)d_in[4];
    const float* wv      = (const float*)d_in[5];
    const float* wo      = (const float*)d_in[6];
    const int*   curpos  = (const int*)d_in[7];
    // d_in[8] = ring_pos (unused)
    float* out = (float*)d_out;

    qkv_gemv<<<160, 1024>>>(x, wq, wk, wv);
    attn_chunk<<<NCHUNK, 256>>>(kv_full, curpos);
    reduce1<<<NGROUP * 16, 256>>>();
    reduce2<<<QROWS / 256, 256>>>();
    wo_gemv<<<80, 1024>>>(wo, out);
}